// round 15
// baseline (speedup 1.0000x reference)
#include <cuda_runtime.h>
#include <cuda_fp16.h>
#include <cstdint>

#define NTOK  4096
#define HID   1024
#define NEXP  16
#define IDIM  2048
#define CAP   768
#define NFLAT (NTOK * 2)

// ---------------- device scratch (no allocs allowed) ----------------
__device__ int   g_flat_sel[NFLAT];
__device__ float g_flat_scale[NFLAT];
__device__ int   g_assign_pos[NFLAT];
__device__ int   g_expert_count[NEXP];
__device__ int   g_expert_tok[NEXP * CAP];

__device__ __align__(256) __half g_x1[(size_t)NEXP * CAP * HID];            // A1 fp16
__device__ __align__(256) __half g_i2[(size_t)NEXP * CAP * IDIM];           // inter fp16
__device__ __align__(256) __half g_w31[(size_t)NEXP * 2 * IDIM * HID];      // B1 fp16
__device__ __align__(256) __half g_w2[(size_t)NEXP * HID * IDIM];           // B2 fp16
__device__ __align__(256) __half g_hbuf[(size_t)NEXP * CAP * 2 * IDIM];     // gemm1 out fp16 (100MB)
__device__ __align__(256) float g_ybuf[(size_t)NEXP * CAP * HID];

// ---------------- helpers ----------------
__device__ __forceinline__ uint32_t smem_u32(const void* p) {
    uint32_t a;
    asm("{ .reg .u64 t; cvta.to.shared.u64 t, %1; cvt.u32.u64 %0, t; }" : "=r"(a) : "l"(p));
    return a;
}
__device__ __forceinline__ void cpa16(uint32_t s, const void* g) {
    asm volatile("cp.async.cg.shared.global [%0], [%1], 16;" :: "r"(s), "l"(g) : "memory");
}
__device__ __forceinline__ void ldsm4(uint32_t& r0, uint32_t& r1, uint32_t& r2, uint32_t& r3,
                                      uint32_t addr) {
    asm volatile("ldmatrix.sync.aligned.m8n8.x4.shared.b16 {%0,%1,%2,%3}, [%4];"
                 : "=r"(r0), "=r"(r1), "=r"(r2), "=r"(r3) : "r"(addr));
}
__device__ __forceinline__ void mma16816(float* c, const uint32_t* a, const uint32_t* b) {
    asm volatile(
        "mma.sync.aligned.m16n8k16.row.col.f32.f16.f16.f32 "
        "{%0,%1,%2,%3}, {%4,%5,%6,%7}, {%8,%9}, {%0,%1,%2,%3};"
        : "+f"(c[0]), "+f"(c[1]), "+f"(c[2]), "+f"(c[3])
        : "r"(a[0]), "r"(a[1]), "r"(a[2]), "r"(a[3]), "r"(b[0]), "r"(b[1]));
}
__device__ __forceinline__ uint32_t pack2h(__half a, __half b) {
    __half2 t(a, b);
    return *reinterpret_cast<uint32_t*>(&t);
}
__device__ __forceinline__ float silu_f(float v) {
    return v / (1.f + __expf(-v));
}
// padded smem tile: 128 rows x 32 fp16 (64B data), row stride 80B -> conflict-free
#define ROW_B 80
#define TILE_B (128 * ROW_B)          // 10240 bytes per operand tile
#define STAGE_B (2 * TILE_B)          // 20480: A | B
#define NSTAGE 3
#define SMEM_BYTES (NSTAGE * STAGE_B) // 61440

// ---------------- routing: softmax top-2 + capacity positions ----------------
__global__ void routing_kernel(const float* __restrict__ logits) {
    __shared__ unsigned char sh_sel[NFLAT];
    const int tid = threadIdx.x;  // 512 threads = 16 warps

    for (int t = tid; t < NTOK; t += 512) {
        const float* l = logits + t * NEXP;
        float l1 = -1e30f, l2 = -1e30f;
        int i1 = 0, i2 = 0;
#pragma unroll
        for (int j = 0; j < NEXP; j++) {
            float v = l[j];
            if (v > l1)      { l2 = l1; i2 = i1; l1 = v; i1 = j; }
            else if (v > l2) { l2 = v; i2 = j; }
        }
        float e2 = __expf(l2 - l1);
        float s1 = 1.f / (1.f + e2);
        g_flat_sel[2 * t]     = i1;
        g_flat_sel[2 * t + 1] = i2;
        g_flat_scale[2 * t]     = s1;
        g_flat_scale[2 * t + 1] = 1.f - s1;
        sh_sel[2 * t]     = (unsigned char)i1;
        sh_sel[2 * t + 1] = (unsigned char)i2;
    }
    __syncthreads();

    const int w = tid >> 5, lane = tid & 31;
    int base = 0;
    for (int c = 0; c < NFLAT; c += 32) {
        int s = sh_sel[c + lane];
        unsigned m = __ballot_sync(0xffffffffu, s == w);
        if (s == w) {
            int pos = base + __popc(m & ((1u << lane) - 1u));
            g_assign_pos[c + lane] = (pos < CAP) ? pos : -1;
            if (pos < CAP) g_expert_tok[w * CAP + pos] = (c + lane) >> 1;
        }
        base += __popc(m);
    }
    if (lane == 0) g_expert_count[w] = base < CAP ? base : CAP;
}

// ---------------- weight convert: f32 -> fp16 (device-resolved dst) ----------------
__global__ void wcvt_kernel(const float* __restrict__ src, int which, int n4) {
    __half* dst = which ? g_w2 : g_w31;
    int stride = gridDim.x * blockDim.x;
    for (int i = blockIdx.x * blockDim.x + threadIdx.x; i < n4; i += stride) {
        float4 v = ((const float4*)src)[i];
        ((uint2*)dst)[i] = make_uint2(
            pack2h(__float2half_rn(v.x), __float2half_rn(v.y)),
            pack2h(__float2half_rn(v.z), __float2half_rn(v.w)));
    }
}

// ---------------- gather rows into contiguous fp16 buffer ----------------
__global__ void gather_kernel(const float* __restrict__ hidden) {
    const int row = blockIdx.x;            // [0, NEXP*CAP)
    const int e = row / CAP, p = row % CAP;
    const int t = threadIdx.x;             // 256, one float4 each
    float4 v = make_float4(0.f, 0.f, 0.f, 0.f);
    if (p < g_expert_count[e]) {
        int tok = g_expert_tok[row];
        v = ((const float4*)(hidden + (size_t)tok * HID))[t];
    }
    *(uint2*)(g_x1 + (size_t)row * HID + t * 4) = make_uint2(
        pack2h(__float2half_rn(v.x), __float2half_rn(v.y)),
        pack2h(__float2half_rn(v.z), __float2half_rn(v.w)));
}

// ---------------- fp16 HMMA GEMM (R10 shape, untouched mainloop) ----------------
// CTA tile 128x128, warp tile 32x64, BK=32, 3-stage cp.async, 256 thr, 2 CTA/SM.
// FIRST: C -> fp16 g_hbuf (packed half2 stores). else: C -> f32 g_ybuf.
template<int NTOT, int K, bool FIRST>
__global__ __launch_bounds__(256, 2) void hmma_gemm() {
    const int e = blockIdx.z;
    if ((int)(blockIdx.y * 128) >= g_expert_count[e]) return;

    extern __shared__ __align__(128) char smem[];
    const uint32_t sb = smem_u32(smem);

    const size_t rowbase = (size_t)e * CAP + (size_t)blockIdx.y * 128;
    const __half* A = (FIRST ? g_x1 : g_i2) + rowbase * K;
    const __half* B = (FIRST ? g_w31 : g_w2)
        + ((size_t)e * NTOT + (size_t)blockIdx.x * 128) * K;

    const int tid = threadIdx.x, lane = tid & 31, warp = tid >> 5;
    const int wm = (warp & 3) * 32, wn = (warp >> 2) * 64;

    const int lrow0 = tid >> 2, lc0 = tid & 3;
    const int lrow1 = lrow0 + 64;
    const uint32_t s0 = (uint32_t)(lrow0 * ROW_B + lc0 * 16);
    const uint32_t s1 = (uint32_t)(lrow1 * ROW_B + lc0 * 16);
    const size_t ga0 = (size_t)lrow0 * K + lc0 * 8;
    const size_t ga1 = (size_t)lrow1 * K + lc0 * 8;

    uint32_t aoff[2][2], boff[4][2];
    {
        const int am = lane & 15, ah = lane >> 4;
        const int mt = lane >> 3;
        const int bn = ((mt >> 1) << 3) + (lane & 7), bh = mt & 1;
#pragma unroll
        for (int i = 0; i < 2; i++)
#pragma unroll
            for (int kk = 0; kk < 2; kk++)
                aoff[i][kk] = (uint32_t)((wm + i * 16 + am) * ROW_B + (kk * 2 + ah) * 16);
#pragma unroll
        for (int j = 0; j < 4; j++)
#pragma unroll
            for (int kk = 0; kk < 2; kk++)
                boff[j][kk] = (uint32_t)((wn + j * 16 + bn) * ROW_B + (kk * 2 + bh) * 16);
    }

    float acc[2][8][4];
#pragma unroll
    for (int i = 0; i < 2; i++)
#pragma unroll
        for (int j = 0; j < 8; j++)
#pragma unroll
            for (int q = 0; q < 4; q++) acc[i][j][q] = 0.f;

    constexpr int NK = K / 32;

    auto load_stage = [&](int kt) {
        const int kl = kt * 32;
        const uint32_t sa = sb + (kt % NSTAGE) * STAGE_B;
        cpa16(sa + s0, A + ga0 + kl);
        cpa16(sa + s1, A + ga1 + kl);
        cpa16(sa + TILE_B + s0, B + ga0 + kl);
        cpa16(sa + TILE_B + s1, B + ga1 + kl);
    };

    load_stage(0);
    asm volatile("cp.async.commit_group;" ::: "memory");
    load_stage(1);
    asm volatile("cp.async.commit_group;" ::: "memory");

    for (int kt = 0; kt < NK; kt++) {
        asm volatile("cp.async.wait_group 1;" ::: "memory");
        __syncthreads();
        if (kt + 2 < NK) load_stage(kt + 2);
        asm volatile("cp.async.commit_group;" ::: "memory");

        const uint32_t sa = sb + (kt % NSTAGE) * STAGE_B, sbf = sa + TILE_B;
#pragma unroll
        for (int kk = 0; kk < 2; kk++) {
            uint32_t aF[2][4], bF[8][2];
            ldsm4(aF[0][0], aF[0][1], aF[0][2], aF[0][3], sa + aoff[0][kk]);
            ldsm4(aF[1][0], aF[1][1], aF[1][2], aF[1][3], sa + aoff[1][kk]);
#pragma unroll
            for (int j = 0; j < 4; j++)
                ldsm4(bF[2 * j][0], bF[2 * j][1], bF[2 * j + 1][0], bF[2 * j + 1][1],
                      sbf + boff[j][kk]);
#pragma unroll
            for (int i = 0; i < 2; i++)
#pragma unroll
                for (int j = 0; j < 8; j++)
                    mma16816(acc[i][j], aF[i], bF[j]);
        }
    }

    const int er = lane >> 2, ec = (lane & 3) * 2;
    if (FIRST) {
        // fp16 packed epilogue: cols (ec, ec+1) adjacent -> one 4B store each
        __half* Ch = g_hbuf + rowbase * NTOT + (size_t)blockIdx.x * 128;
#pragma unroll
        for (int i = 0; i < 2; i++) {
#pragma unroll
            for (int j = 0; j < 8; j++) {
                __half* p0 = Ch + (size_t)(wm + i * 16 + er) * NTOT + wn + j * 8 + ec;
                __half* p1 = p0 + (size_t)8 * NTOT;
                *(uint32_t*)p0 = pack2h(__float2half_rn(acc[i][j][0]),
                                        __float2half_rn(acc[i][j][1]));
                *(uint32_t*)p1 = pack2h(__float2half_rn(acc[i][j][2]),
                                        __float2half_rn(acc[i][j][3]));
            }
        }
    } else {
        float* C = g_ybuf + rowbase * NTOT + (size_t)blockIdx.x * 128;
#pragma unroll
        for (int i = 0; i < 2; i++) {
#pragma unroll
            for (int j = 0; j < 8; j++) {
                float* p0 = C + (size_t)(wm + i * 16 + er) * NTOT + wn + j * 8 + ec;
                float* p1 = p0 + (size_t)8 * NTOT;
                *(float2*)p0 = make_float2(acc[i][j][0], acc[i][j][1]);
                *(float2*)p1 = make_float2(acc[i][j][2], acc[i][j][3]);
            }
        }
    }
}

// ---------------- activation: inter = g3 * silu(g1), fp16 in / fp16 out ----------------
__global__ void act_kernel() {
    size_t idx8 = (size_t)blockIdx.x * 256 + threadIdx.x;   // 8-half groups
    size_t row = idx8 >> 8;            // IDIM/8 = 256 groups per row
    int c8 = (int)(idx8 & 255);
    const __half* hrow = g_hbuf + row * (2 * IDIM);
    uint4 g3v = *(const uint4*)(hrow + c8 * 8);
    uint4 g1v = *(const uint4*)(hrow + IDIM + c8 * 8);
    const __half2* g3h = (const __half2*)&g3v;
    const __half2* g1h = (const __half2*)&g1v;
    uint4 o;
    uint32_t* op = (uint32_t*)&o;
#pragma unroll
    for (int q = 0; q < 4; q++) {
        float2 a = __half22float2(g3h[q]);
        float2 b = __half22float2(g1h[q]);
        op[q] = pack2h(__float2half_rn(a.x * silu_f(b.x)),
                       __float2half_rn(a.y * silu_f(b.y)));
    }
    *(uint4*)(g_i2 + row * IDIM + c8 * 8) = o;
}

// ---------------- scatter back: out[t] = sum_k scale * y[e, pos] ----------------
__global__ void scatter_kernel(float* __restrict__ out) {
    const int t = blockIdx.x;
    const int tid = threadIdx.x;  // 256, one float4 each
    float4 acc = make_float4(0.f, 0.f, 0.f, 0.f);
#pragma unroll
    for (int k = 0; k < 2; k++) {
        int f = 2 * t + k;
        int pos = g_assign_pos[f];
        if (pos >= 0) {
            int e = g_flat_sel[f];
            float s = g_flat_scale[f];
            float4 v = ((const float4*)(g_ybuf + (size_t)(e * CAP + pos) * HID))[tid];
            acc.x += s * v.x; acc.y += s * v.y; acc.z += s * v.z; acc.w += s * v.w;
        }
    }
    ((float4*)(out + (size_t)t * HID))[tid] = acc;
}

// ---------------- launch ----------------
extern "C" void kernel_launch(void* const* d_in, const int* in_sizes, int n_in,
                              void* d_out, int out_size) {
    const float* hidden = (const float*)d_in[0];
    const float* logits = (const float*)d_in[1];
    const float* w31    = (const float*)d_in[2];
    const float* w2     = (const float*)d_in[3];
    float* out = (float*)d_out;

    static int smem_set = 0;
    if (!smem_set) {
        cudaFuncSetAttribute(hmma_gemm<2 * IDIM, HID, true>,
                             cudaFuncAttributeMaxDynamicSharedMemorySize, SMEM_BYTES);
        cudaFuncSetAttribute(hmma_gemm<HID, IDIM, false>,
                             cudaFuncAttributeMaxDynamicSharedMemorySize, SMEM_BYTES);
        smem_set = 1;
    }

    routing_kernel<<<1, 512>>>(logits);
    gather_kernel<<<NEXP * CAP, 256>>>(hidden);
    wcvt_kernel<<<4096, 256>>>(w31, 0, NEXP * 2 * IDIM * HID / 4);
    wcvt_kernel<<<4096, 256>>>(w2, 1, NEXP * HID * IDIM / 4);
    hmma_gemm<2 * IDIM, HID, true><<<dim3(32, 6, NEXP), 256, SMEM_BYTES>>>();
    act_kernel<<<(int)(((size_t)NEXP * CAP * IDIM / 8) / 256), 256>>>();
    hmma_gemm<HID, IDIM, false><<<dim3(8, 6, NEXP), 256, SMEM_BYTES>>>();
    scatter_kernel<<<NTOK, 256>>>(out);
}

// round 16
// speedup vs baseline: 1.0335x; 1.0335x over previous
#include <cuda_runtime.h>
#include <cuda_fp16.h>
#include <cstdint>

#define NTOK  4096
#define HID   1024
#define NEXP  16
#define IDIM  2048
#define CAP   768
#define NFLAT (NTOK * 2)

// ---------------- device scratch (no allocs allowed) ----------------
__device__ int   g_flat_sel[NFLAT];
__device__ float g_flat_scale[NFLAT];
__device__ int   g_assign_pos[NFLAT];
__device__ int   g_expert_count[NEXP];
__device__ int   g_expert_tok[NEXP * CAP];

__device__ __align__(256) __half g_x1[(size_t)NEXP * CAP * HID];          // A1 fp16
__device__ __align__(256) __half g_i2[(size_t)NEXP * CAP * IDIM];         // inter fp16
__device__ __align__(256) float g_hbuf[(size_t)NEXP * CAP * 2 * IDIM];    // gemm1 out f32
__device__ __align__(256) float g_ybuf[(size_t)NEXP * CAP * HID];         // gemm2 out f32

// ---------------- helpers ----------------
__device__ __forceinline__ uint32_t smem_u32(const void* p) {
    uint32_t a;
    asm("{ .reg .u64 t; cvta.to.shared.u64 t, %1; cvt.u32.u64 %0, t; }" : "=r"(a) : "l"(p));
    return a;
}
__device__ __forceinline__ void cpa16(uint32_t s, const void* g) {
    asm volatile("cp.async.cg.shared.global [%0], [%1], 16;" :: "r"(s), "l"(g) : "memory");
}
__device__ __forceinline__ void ldsm4(uint32_t& r0, uint32_t& r1, uint32_t& r2, uint32_t& r3,
                                      uint32_t addr) {
    asm volatile("ldmatrix.sync.aligned.m8n8.x4.shared.b16 {%0,%1,%2,%3}, [%4];"
                 : "=r"(r0), "=r"(r1), "=r"(r2), "=r"(r3) : "r"(addr));
}
__device__ __forceinline__ void mma16816(float* c, const uint32_t* a, const uint32_t* b) {
    asm volatile(
        "mma.sync.aligned.m16n8k16.row.col.f32.f16.f16.f32 "
        "{%0,%1,%2,%3}, {%4,%5,%6,%7}, {%8,%9}, {%0,%1,%2,%3};"
        : "+f"(c[0]), "+f"(c[1]), "+f"(c[2]), "+f"(c[3])
        : "r"(a[0]), "r"(a[1]), "r"(a[2]), "r"(a[3]), "r"(b[0]), "r"(b[1]));
}
__device__ __forceinline__ uint32_t pack2h(__half a, __half b) {
    __half2 t(a, b);
    return *reinterpret_cast<uint32_t*>(&t);
}
__device__ __forceinline__ uint4 cvt8(float4 a, float4 b) {
    uint4 r;
    r.x = pack2h(__float2half_rn(a.x), __float2half_rn(a.y));
    r.y = pack2h(__float2half_rn(a.z), __float2half_rn(a.w));
    r.z = pack2h(__float2half_rn(b.x), __float2half_rn(b.y));
    r.w = pack2h(__float2half_rn(b.z), __float2half_rn(b.w));
    return r;
}
// padded smem tile: 128 rows x 32 fp16 (64B data), row stride 80B -> conflict-free
#define ROW_B 80
#define TILE_B (128 * ROW_B)          // 10240 bytes per operand tile
#define STAGE_B (2 * TILE_B)          // 20480: A | B
#define NSTAGE 3
#define SMEM_BYTES (NSTAGE * STAGE_B) // 61440

// ---------------- routing: softmax top-2 + capacity positions ----------------
__global__ void routing_kernel(const float* __restrict__ logits) {
    __shared__ unsigned char sh_sel[NFLAT];
    const int tid = threadIdx.x;  // 512 threads = 16 warps

    for (int t = tid; t < NTOK; t += 512) {
        const float* l = logits + t * NEXP;
        float l1 = -1e30f, l2 = -1e30f;
        int i1 = 0, i2 = 0;
#pragma unroll
        for (int j = 0; j < NEXP; j++) {
            float v = l[j];
            if (v > l1)      { l2 = l1; i2 = i1; l1 = v; i1 = j; }
            else if (v > l2) { l2 = v; i2 = j; }
        }
        float e2 = __expf(l2 - l1);
        float s1 = 1.f / (1.f + e2);
        g_flat_sel[2 * t]     = i1;
        g_flat_sel[2 * t + 1] = i2;
        g_flat_scale[2 * t]     = s1;
        g_flat_scale[2 * t + 1] = 1.f - s1;
        sh_sel[2 * t]     = (unsigned char)i1;
        sh_sel[2 * t + 1] = (unsigned char)i2;
    }
    __syncthreads();

    const int w = tid >> 5, lane = tid & 31;
    int base = 0;
    for (int c = 0; c < NFLAT; c += 32) {
        int s = sh_sel[c + lane];
        unsigned m = __ballot_sync(0xffffffffu, s == w);
        if (s == w) {
            int pos = base + __popc(m & ((1u << lane) - 1u));
            g_assign_pos[c + lane] = (pos < CAP) ? pos : -1;
            if (pos < CAP) g_expert_tok[w * CAP + pos] = (c + lane) >> 1;
        }
        base += __popc(m);
    }
    if (lane == 0) g_expert_count[w] = base < CAP ? base : CAP;
}

// ---------------- gather rows into contiguous fp16 buffer ----------------
__global__ void gather_kernel(const float* __restrict__ hidden) {
    const int row = blockIdx.x;            // [0, NEXP*CAP)
    const int e = row / CAP, p = row % CAP;
    const int t = threadIdx.x;             // 256, one float4 each
    float4 v = make_float4(0.f, 0.f, 0.f, 0.f);
    if (p < g_expert_count[e]) {
        int tok = g_expert_tok[row];
        v = ((const float4*)(hidden + (size_t)tok * HID))[t];
    }
    *(uint2*)(g_x1 + (size_t)row * HID + t * 4) = make_uint2(
        pack2h(__float2half_rn(v.x), __float2half_rn(v.y)),
        pack2h(__float2half_rn(v.z), __float2half_rn(v.w)));
}

// ---------------- fp16 HMMA GEMM, R10 mainloop, B loaded f32 + converted inline ----------------
// CTA tile 128x128, warp tile 32x64, BK=32, A: 3-stage cp.async (fp16); B: f32 LDG
// register-prefetch one stage ahead -> __float2half_rn -> smem fp16 (same slots as R10).
template<int NTOT, int K, bool FIRST>
__global__ __launch_bounds__(256, 2) void hmma_gemm(const float* __restrict__ Bf) {
    const int e = blockIdx.z;
    if ((int)(blockIdx.y * 128) >= g_expert_count[e]) return;

    extern __shared__ __align__(128) char smem[];
    const uint32_t sb = smem_u32(smem);

    const size_t rowbase = (size_t)e * CAP + (size_t)blockIdx.y * 128;
    const __half* A = (FIRST ? g_x1 : g_i2) + rowbase * K;
    const float* B = Bf + ((size_t)e * NTOT + (size_t)blockIdx.x * 128) * K;

    const int tid = threadIdx.x, lane = tid & 31, warp = tid >> 5;
    const int wm = (warp & 3) * 32, wn = (warp >> 2) * 64;

    // load map: rows (tid>>2), (tid>>2)+64, element chunk (tid&3)*8 within BK=32
    const int lrow0 = tid >> 2, lc0 = tid & 3;
    const int lrow1 = lrow0 + 64;
    const uint32_t s0 = (uint32_t)(lrow0 * ROW_B + lc0 * 16);
    const uint32_t s1 = (uint32_t)(lrow1 * ROW_B + lc0 * 16);
    const size_t ga0 = (size_t)lrow0 * K + lc0 * 8;   // element index (halves or floats)
    const size_t ga1 = (size_t)lrow1 * K + lc0 * 8;

    // ldmatrix per-lane offsets (verified coordinates R7-R15)
    uint32_t aoff[2][2], boff[4][2];
    {
        const int am = lane & 15, ah = lane >> 4;
        const int mt = lane >> 3;
        const int bn = ((mt >> 1) << 3) + (lane & 7), bh = mt & 1;
#pragma unroll
        for (int i = 0; i < 2; i++)
#pragma unroll
            for (int kk = 0; kk < 2; kk++)
                aoff[i][kk] = (uint32_t)((wm + i * 16 + am) * ROW_B + (kk * 2 + ah) * 16);
#pragma unroll
        for (int j = 0; j < 4; j++)
#pragma unroll
            for (int kk = 0; kk < 2; kk++)
                boff[j][kk] = (uint32_t)((wn + j * 16 + bn) * ROW_B + (kk * 2 + bh) * 16);
    }

    float acc[2][8][4];
#pragma unroll
    for (int i = 0; i < 2; i++)
#pragma unroll
        for (int j = 0; j < 8; j++)
#pragma unroll
            for (int q = 0; q < 4; q++) acc[i][j][q] = 0.f;

    constexpr int NK = K / 32;

    auto cpaA = [&](int kt) {
        const int kl = kt * 32;
        const uint32_t sa = sb + (kt % NSTAGE) * STAGE_B;
        cpa16(sa + s0, A + ga0 + kl);
        cpa16(sa + s1, A + ga1 + kl);
    };

    float4 b00, b01, b10, b11;   // B prefetch registers (one stage)
    auto gloadB = [&](int kt) {
        const int kl = kt * 32;
        const float* p0 = B + ga0 + kl;
        const float* p1 = B + ga1 + kl;
        b00 = *(const float4*)(p0);
        b01 = *(const float4*)(p0 + 4);
        b10 = *(const float4*)(p1);
        b11 = *(const float4*)(p1 + 4);
    };
    auto sstoreB = [&](int kt) {
        const uint32_t sbf = sb + (kt % NSTAGE) * STAGE_B + TILE_B;
        *(uint4*)(smem + (sbf - sb) + s0) = cvt8(b00, b01);
        *(uint4*)(smem + (sbf - sb) + s1) = cvt8(b10, b11);
    };

    // prologue
    gloadB(0);
    cpaA(0);
    asm volatile("cp.async.commit_group;" ::: "memory");
    cpaA(1);
    asm volatile("cp.async.commit_group;" ::: "memory");
    sstoreB(0);
    gloadB(1);

    for (int kt = 0; kt < NK; kt++) {
        asm volatile("cp.async.wait_group 1;" ::: "memory");
        __syncthreads();                       // A(kt) + B(kt) visible
        if (kt + 2 < NK) cpaA(kt + 2);
        asm volatile("cp.async.commit_group;" ::: "memory");
        // store B(kt+1) into buffer (kt+1)%3: last readers were stage kt-2 (done)
        if (kt + 1 < NK) sstoreB(kt + 1);
        if (kt + 2 < NK) gloadB(kt + 2);       // prefetch next-next

        const uint32_t sa = sb + (kt % NSTAGE) * STAGE_B, sbf = sa + TILE_B;
#pragma unroll
        for (int kk = 0; kk < 2; kk++) {
            uint32_t aF[2][4], bF[8][2];
            ldsm4(aF[0][0], aF[0][1], aF[0][2], aF[0][3], sa + aoff[0][kk]);
            ldsm4(aF[1][0], aF[1][1], aF[1][2], aF[1][3], sa + aoff[1][kk]);
#pragma unroll
            for (int j = 0; j < 4; j++)
                ldsm4(bF[2 * j][0], bF[2 * j][1], bF[2 * j + 1][0], bF[2 * j + 1][1],
                      sbf + boff[j][kk]);
#pragma unroll
            for (int i = 0; i < 2; i++)
#pragma unroll
                for (int j = 0; j < 8; j++)
                    mma16816(acc[i][j], aF[i], bF[j]);
        }
    }

    // epilogue: standard m16n8 C layout, f32 stores (R10-identical)
    float* C = (FIRST ? g_hbuf : g_ybuf) + rowbase * NTOT + (size_t)blockIdx.x * 128;
    const int er = lane >> 2, ec = (lane & 3) * 2;
#pragma unroll
    for (int i = 0; i < 2; i++) {
#pragma unroll
        for (int j = 0; j < 8; j++) {
            float* p0 = C + (size_t)(wm + i * 16 + er) * NTOT + wn + j * 8 + ec;
            float* p1 = p0 + (size_t)8 * NTOT;
            *(float2*)p0 = make_float2(acc[i][j][0], acc[i][j][1]);
            *(float2*)p1 = make_float2(acc[i][j][2], acc[i][j][3]);
        }
    }
}

// ---------------- activation: inter = g3 * silu(g1) -> fp16 (R10 version) ----------------
__global__ void act_kernel() {
    size_t idx4 = (size_t)blockIdx.x * 256 + threadIdx.x;   // float4 groups
    size_t row = idx4 >> 9;            // IDIM/4 = 512 groups per row
    int c4 = (int)(idx4 & 511);
    const float* hrow = g_hbuf + row * (2 * IDIM);
    float4 g3 = *(const float4*)(hrow + c4 * 4);
    float4 g1 = *(const float4*)(hrow + IDIM + c4 * 4);
    float4 o;
    o.x = g3.x * (g1.x / (1.f + __expf(-g1.x)));
    o.y = g3.y * (g1.y / (1.f + __expf(-g1.y)));
    o.z = g3.z * (g1.z / (1.f + __expf(-g1.z)));
    o.w = g3.w * (g1.w / (1.f + __expf(-g1.w)));
    *(uint2*)(g_i2 + row * IDIM + c4 * 4) = make_uint2(
        pack2h(__float2half_rn(o.x), __float2half_rn(o.y)),
        pack2h(__float2half_rn(o.z), __float2half_rn(o.w)));
}

// ---------------- scatter back: out[t] = sum_k scale * y[e, pos] ----------------
__global__ void scatter_kernel(float* __restrict__ out) {
    const int t = blockIdx.x;
    const int tid = threadIdx.x;  // 256, one float4 each
    float4 acc = make_float4(0.f, 0.f, 0.f, 0.f);
#pragma unroll
    for (int k = 0; k < 2; k++) {
        int f = 2 * t + k;
        int pos = g_assign_pos[f];
        if (pos >= 0) {
            int e = g_flat_sel[f];
            float s = g_flat_scale[f];
            float4 v = ((const float4*)(g_ybuf + (size_t)(e * CAP + pos) * HID))[tid];
            acc.x += s * v.x; acc.y += s * v.y; acc.z += s * v.z; acc.w += s * v.w;
        }
    }
    ((float4*)(out + (size_t)t * HID))[tid] = acc;
}

// ---------------- launch ----------------
extern "C" void kernel_launch(void* const* d_in, const int* in_sizes, int n_in,
                              void* d_out, int out_size) {
    const float* hidden = (const float*)d_in[0];
    const float* logits = (const float*)d_in[1];
    const float* w31    = (const float*)d_in[2];
    const float* w2     = (const float*)d_in[3];
    float* out = (float*)d_out;

    static int smem_set = 0;
    if (!smem_set) {
        cudaFuncSetAttribute(hmma_gemm<2 * IDIM, HID, true>,
                             cudaFuncAttributeMaxDynamicSharedMemorySize, SMEM_BYTES);
        cudaFuncSetAttribute(hmma_gemm<HID, IDIM, false>,
                             cudaFuncAttributeMaxDynamicSharedMemorySize, SMEM_BYTES);
        smem_set = 1;
    }

    routing_kernel<<<1, 512>>>(logits);
    gather_kernel<<<NEXP * CAP, 256>>>(hidden);
    hmma_gemm<2 * IDIM, HID, true><<<dim3(32, 6, NEXP), 256, SMEM_BYTES>>>(w31);
    act_kernel<<<(int)(((size_t)NEXP * CAP * IDIM / 4) / 256), 256>>>();
    hmma_gemm<HID, IDIM, false><<<dim3(8, 6, NEXP), 256, SMEM_BYTES>>>(w2);
    scatter_kernel<<<NTOK, 256>>>(out);
}

// round 17
// speedup vs baseline: 1.1051x; 1.0693x over previous
#include <cuda_runtime.h>
#include <cuda_fp16.h>
#include <cstdint>

#define NTOK  4096
#define HID   1024
#define NEXP  16
#define IDIM  2048
#define CAP   768
#define NFLAT (NTOK * 2)

// ---------------- device scratch (no allocs allowed) ----------------
__device__ int   g_flat_sel[NFLAT];
__device__ float g_flat_scale[NFLAT];
__device__ int   g_assign_pos[NFLAT];
__device__ int   g_expert_count[NEXP];
__device__ int   g_expert_tok[NEXP * CAP];

__device__ __align__(256) __half g_x1[(size_t)NEXP * CAP * HID];          // A1 fp16
__device__ __align__(256) __half g_i2[(size_t)NEXP * CAP * IDIM];         // inter fp16
__device__ __align__(256) __half g_w31[(size_t)NEXP * 2 * IDIM * HID];    // B1 fp16
__device__ __align__(256) __half g_w2[(size_t)NEXP * HID * IDIM];         // B2 fp16
__device__ __align__(256) float g_hbuf[(size_t)NEXP * CAP * 2 * IDIM];    // gemm1 out f32
__device__ __align__(256) float g_ybuf[(size_t)NEXP * CAP * HID];         // gemm2 out f32

// ---------------- helpers ----------------
__device__ __forceinline__ uint32_t smem_u32(const void* p) {
    uint32_t a;
    asm("{ .reg .u64 t; cvta.to.shared.u64 t, %1; cvt.u32.u64 %0, t; }" : "=r"(a) : "l"(p));
    return a;
}
__device__ __forceinline__ void cpa16(uint32_t s, const void* g) {
    asm volatile("cp.async.cg.shared.global [%0], [%1], 16;" :: "r"(s), "l"(g) : "memory");
}
__device__ __forceinline__ void ldsm4(uint32_t& r0, uint32_t& r1, uint32_t& r2, uint32_t& r3,
                                      uint32_t addr) {
    asm volatile("ldmatrix.sync.aligned.m8n8.x4.shared.b16 {%0,%1,%2,%3}, [%4];"
                 : "=r"(r0), "=r"(r1), "=r"(r2), "=r"(r3) : "r"(addr));
}
__device__ __forceinline__ void mma16816(float* c, const uint32_t* a, const uint32_t* b) {
    asm volatile(
        "mma.sync.aligned.m16n8k16.row.col.f32.f16.f16.f32 "
        "{%0,%1,%2,%3}, {%4,%5,%6,%7}, {%8,%9}, {%0,%1,%2,%3};"
        : "+f"(c[0]), "+f"(c[1]), "+f"(c[2]), "+f"(c[3])
        : "r"(a[0]), "r"(a[1]), "r"(a[2]), "r"(a[3]), "r"(b[0]), "r"(b[1]));
}
__device__ __forceinline__ uint32_t pack2h(__half a, __half b) {
    __half2 t(a, b);
    return *reinterpret_cast<uint32_t*>(&t);
}
// padded smem tile: 128 rows x 32 fp16 (64B data), row stride 80B -> conflict-free
#define ROW_B 80
#define TILE_B (128 * ROW_B)          // 10240 bytes per operand tile
#define STAGE_B (2 * TILE_B)          // 20480: A | B
#define NSTAGE 3
#define SMEM_BYTES (NSTAGE * STAGE_B) // 61440

// ---------------- routing: softmax top-2 + capacity positions ----------------
__global__ void routing_kernel(const float* __restrict__ logits) {
    __shared__ unsigned char sh_sel[NFLAT];
    const int tid = threadIdx.x;  // 512 threads = 16 warps

    for (int t = tid; t < NTOK; t += 512) {
        const float* l = logits + t * NEXP;
        float l1 = -1e30f, l2 = -1e30f;
        int i1 = 0, i2 = 0;
#pragma unroll
        for (int j = 0; j < NEXP; j++) {
            float v = l[j];
            if (v > l1)      { l2 = l1; i2 = i1; l1 = v; i1 = j; }
            else if (v > l2) { l2 = v; i2 = j; }
        }
        float e2 = __expf(l2 - l1);
        float s1 = 1.f / (1.f + e2);
        g_flat_sel[2 * t]     = i1;
        g_flat_sel[2 * t + 1] = i2;
        g_flat_scale[2 * t]     = s1;
        g_flat_scale[2 * t + 1] = 1.f - s1;
        sh_sel[2 * t]     = (unsigned char)i1;
        sh_sel[2 * t + 1] = (unsigned char)i2;
    }
    __syncthreads();

    const int w = tid >> 5, lane = tid & 31;
    int base = 0;
    for (int c = 0; c < NFLAT; c += 32) {
        int s = sh_sel[c + lane];
        unsigned m = __ballot_sync(0xffffffffu, s == w);
        if (s == w) {
            int pos = base + __popc(m & ((1u << lane) - 1u));
            g_assign_pos[c + lane] = (pos < CAP) ? pos : -1;
            if (pos < CAP) g_expert_tok[w * CAP + pos] = (c + lane) >> 1;
        }
        base += __popc(m);
    }
    if (lane == 0) g_expert_count[w] = base < CAP ? base : CAP;
}

// ---------------- weight convert: f32 -> fp16 (device-resolved dst) ----------------
__global__ void wcvt_kernel(const float* __restrict__ src, int which, int n4) {
    __half* dst = which ? g_w2 : g_w31;
    int stride = gridDim.x * blockDim.x;
    for (int i = blockIdx.x * blockDim.x + threadIdx.x; i < n4; i += stride) {
        float4 v = ((const float4*)src)[i];
        ((uint2*)dst)[i] = make_uint2(
            pack2h(__float2half_rn(v.x), __float2half_rn(v.y)),
            pack2h(__float2half_rn(v.z), __float2half_rn(v.w)));
    }
}

// ---------------- gather rows into contiguous fp16 buffer ----------------
__global__ void gather_kernel(const float* __restrict__ hidden) {
    const int row = blockIdx.x;            // [0, NEXP*CAP)
    const int e = row / CAP, p = row % CAP;
    const int t = threadIdx.x;             // 256, one float4 each
    float4 v = make_float4(0.f, 0.f, 0.f, 0.f);
    if (p < g_expert_count[e]) {
        int tok = g_expert_tok[row];
        v = ((const float4*)(hidden + (size_t)tok * HID))[t];
    }
    *(uint2*)(g_x1 + (size_t)row * HID + t * 4) = make_uint2(
        pack2h(__float2half_rn(v.x), __float2half_rn(v.y)),
        pack2h(__float2half_rn(v.z), __float2half_rn(v.w)));
}

// ---------------- fp16 HMMA GEMM (R10 exact) ----------------
// CTA tile 128x128, warp tile 32x64, BK=32 fp16, 3-stage cp.async, 256 thr, 2 CTA/SM.
template<int NTOT, int K, bool FIRST>
__global__ __launch_bounds__(256, 2) void hmma_gemm() {
    const int e = blockIdx.z;
    if ((int)(blockIdx.y * 128) >= g_expert_count[e]) return;

    extern __shared__ __align__(128) char smem[];
    const uint32_t sb = smem_u32(smem);

    const __half* A = (FIRST ? g_x1 : g_i2)
        + ((size_t)e * CAP + (size_t)blockIdx.y * 128) * K;
    const __half* B = (FIRST ? g_w31 : g_w2)
        + ((size_t)e * NTOT + (size_t)blockIdx.x * 128) * K;
    float* C = (FIRST ? g_hbuf : g_ybuf)
        + ((size_t)e * CAP + (size_t)blockIdx.y * 128) * NTOT + (size_t)blockIdx.x * 128;

    const int tid = threadIdx.x, lane = tid & 31, warp = tid >> 5;
    const int wm = (warp & 3) * 32, wn = (warp >> 2) * 64;

    const int lrow0 = tid >> 2, lc0 = tid & 3;
    const int lrow1 = lrow0 + 64;
    const uint32_t s0 = (uint32_t)(lrow0 * ROW_B + lc0 * 16);
    const uint32_t s1 = (uint32_t)(lrow1 * ROW_B + lc0 * 16);
    const size_t ga0 = (size_t)lrow0 * K + lc0 * 8;
    const size_t ga1 = (size_t)lrow1 * K + lc0 * 8;

    uint32_t aoff[2][2], boff[4][2];
    {
        const int am = lane & 15, ah = lane >> 4;
        const int mt = lane >> 3;
        const int bn = ((mt >> 1) << 3) + (lane & 7), bh = mt & 1;
#pragma unroll
        for (int i = 0; i < 2; i++)
#pragma unroll
            for (int kk = 0; kk < 2; kk++)
                aoff[i][kk] = (uint32_t)((wm + i * 16 + am) * ROW_B + (kk * 2 + ah) * 16);
#pragma unroll
        for (int j = 0; j < 4; j++)
#pragma unroll
            for (int kk = 0; kk < 2; kk++)
                boff[j][kk] = (uint32_t)((wn + j * 16 + bn) * ROW_B + (kk * 2 + bh) * 16);
    }

    float acc[2][8][4];
#pragma unroll
    for (int i = 0; i < 2; i++)
#pragma unroll
        for (int j = 0; j < 8; j++)
#pragma unroll
            for (int q = 0; q < 4; q++) acc[i][j][q] = 0.f;

    constexpr int NK = K / 32;

    auto load_stage = [&](int kt) {
        const int kl = kt * 32;
        const uint32_t sa = sb + (kt % NSTAGE) * STAGE_B;
        cpa16(sa + s0, A + ga0 + kl);
        cpa16(sa + s1, A + ga1 + kl);
        cpa16(sa + TILE_B + s0, B + ga0 + kl);
        cpa16(sa + TILE_B + s1, B + ga1 + kl);
    };

    load_stage(0);
    asm volatile("cp.async.commit_group;" ::: "memory");
    load_stage(1);
    asm volatile("cp.async.commit_group;" ::: "memory");

    for (int kt = 0; kt < NK; kt++) {
        asm volatile("cp.async.wait_group 1;" ::: "memory");
        __syncthreads();
        if (kt + 2 < NK) load_stage(kt + 2);
        asm volatile("cp.async.commit_group;" ::: "memory");

        const uint32_t sa = sb + (kt % NSTAGE) * STAGE_B, sbf = sa + TILE_B;
#pragma unroll
        for (int kk = 0; kk < 2; kk++) {
            uint32_t aF[2][4], bF[8][2];
            ldsm4(aF[0][0], aF[0][1], aF[0][2], aF[0][3], sa + aoff[0][kk]);
            ldsm4(aF[1][0], aF[1][1], aF[1][2], aF[1][3], sa + aoff[1][kk]);
#pragma unroll
            for (int j = 0; j < 4; j++)
                ldsm4(bF[2 * j][0], bF[2 * j][1], bF[2 * j + 1][0], bF[2 * j + 1][1],
                      sbf + boff[j][kk]);
#pragma unroll
            for (int i = 0; i < 2; i++)
#pragma unroll
                for (int j = 0; j < 8; j++)
                    mma16816(acc[i][j], aF[i], bF[j]);
        }
    }

    const int er = lane >> 2, ec = (lane & 3) * 2;
#pragma unroll
    for (int i = 0; i < 2; i++) {
#pragma unroll
        for (int j = 0; j < 8; j++) {
            float* p0 = C + (size_t)(wm + i * 16 + er) * NTOT + wn + j * 8 + ec;
            float* p1 = p0 + (size_t)8 * NTOT;
            *(float2*)p0 = make_float2(acc[i][j][0], acc[i][j][1]);
            *(float2*)p1 = make_float2(acc[i][j][2], acc[i][j][3]);
        }
    }
}

// ---------------- activation: inter = g3 * silu(g1) -> fp16 ----------------
__global__ void act_kernel() {
    size_t idx4 = (size_t)blockIdx.x * 256 + threadIdx.x;   // float4 groups
    size_t row = idx4 >> 9;            // IDIM/4 = 512 groups per row
    int c4 = (int)(idx4 & 511);
    const float* hrow = g_hbuf + row * (2 * IDIM);
    float4 g3 = *(const float4*)(hrow + c4 * 4);
    float4 g1 = *(const float4*)(hrow + IDIM + c4 * 4);
    float4 o;
    o.x = g3.x * (g1.x / (1.f + __expf(-g1.x)));
    o.y = g3.y * (g1.y / (1.f + __expf(-g1.y)));
    o.z = g3.z * (g1.z / (1.f + __expf(-g1.z)));
    o.w = g3.w * (g1.w / (1.f + __expf(-g1.w)));
    *(uint2*)(g_i2 + row * IDIM + c4 * 4) = make_uint2(
        pack2h(__float2half_rn(o.x), __float2half_rn(o.y)),
        pack2h(__float2half_rn(o.z), __float2half_rn(o.w)));
}

// ---------------- scatter back: out[t] = sum_k scale * y[e, pos] ----------------
__global__ void scatter_kernel(float* __restrict__ out) {
    const int t = blockIdx.x;
    const int tid = threadIdx.x;  // 256, one float4 each
    float4 acc = make_float4(0.f, 0.f, 0.f, 0.f);
#pragma unroll
    for (int k = 0; k < 2; k++) {
        int f = 2 * t + k;
        int pos = g_assign_pos[f];
        if (pos >= 0) {
            int e = g_flat_sel[f];
            float s = g_flat_scale[f];
            float4 v = ((const float4*)(g_ybuf + (size_t)(e * CAP + pos) * HID))[tid];
            acc.x += s * v.x; acc.y += s * v.y; acc.z += s * v.z; acc.w += s * v.w;
        }
    }
    ((float4*)(out + (size_t)t * HID))[tid] = acc;
}

// ---------------- launch: side-stream overlap of weight conversion ----------------
extern "C" void kernel_launch(void* const* d_in, const int* in_sizes, int n_in,
                              void* d_out, int out_size) {
    const float* hidden = (const float*)d_in[0];
    const float* logits = (const float*)d_in[1];
    const float* w31    = (const float*)d_in[2];
    const float* w2     = (const float*)d_in[3];
    float* out = (float*)d_out;

    static cudaStream_t s1;
    static cudaEvent_t ev0, ev1, ev2;
    static int init_done = 0;
    if (!init_done) {
        cudaFuncSetAttribute(hmma_gemm<2 * IDIM, HID, true>,
                             cudaFuncAttributeMaxDynamicSharedMemorySize, SMEM_BYTES);
        cudaFuncSetAttribute(hmma_gemm<HID, IDIM, false>,
                             cudaFuncAttributeMaxDynamicSharedMemorySize, SMEM_BYTES);
        cudaStreamCreateWithFlags(&s1, cudaStreamNonBlocking);
        cudaEventCreateWithFlags(&ev0, cudaEventDisableTiming);
        cudaEventCreateWithFlags(&ev1, cudaEventDisableTiming);
        cudaEventCreateWithFlags(&ev2, cudaEventDisableTiming);
        init_done = 1;
    }

    // fork side stream from the (possibly capturing) default stream
    cudaEventRecord(ev0, 0);
    cudaStreamWaitEvent(s1, ev0, 0);
    // side stream: w31 convert (gates gemm1), then w2 convert (overlaps gemm1)
    wcvt_kernel<<<4096, 256, 0, s1>>>(w31, 0, NEXP * 2 * IDIM * HID / 4);
    cudaEventRecord(ev1, s1);
    wcvt_kernel<<<4096, 256, 0, s1>>>(w2, 1, NEXP * HID * IDIM / 4);
    cudaEventRecord(ev2, s1);

    // main stream
    routing_kernel<<<1, 512>>>(logits);
    gather_kernel<<<NEXP * CAP, 256>>>(hidden);
    cudaStreamWaitEvent(0, ev1, 0);   // need w31 fp16
    hmma_gemm<2 * IDIM, HID, true><<<dim3(32, 6, NEXP), 256, SMEM_BYTES>>>();
    act_kernel<<<(int)(((size_t)NEXP * CAP * IDIM / 4) / 256), 256>>>();
    cudaStreamWaitEvent(0, ev2, 0);   // need w2 fp16
    hmma_gemm<HID, IDIM, false><<<dim3(8, 6, NEXP), 256, SMEM_BYTES>>>();
    scatter_kernel<<<NTOK, 256>>>(out);
}